// round 2
// baseline (speedup 1.0000x reference)
#include <cuda_runtime.h>
#include <math.h>

#define BATCH 256
#define DIM   512
#define NCLS  100000
#define NSUB  3
#define MROWS (NCLS*NSUB)

#define BM 48
#define BK 32

#define CPC 125
#define NCHUNK (NCLS/CPC)   // 800 exactly

// ArcFace constants (margin = 0.5)
#define COS_M 0.8775825618903728f
#define SIN_M 0.479425538604203f
#define TH_C  (-0.8775825618903728f)
#define MM_C  0.2397127693021015f
#define SCALE_C 64.0f

// ---------------- scratch (device globals; no allocation allowed) ----------
__device__ float g_eT[DIM * BATCH];            // embeddings normalized, [k][n]
__device__ float g_inv_wn[MROWS];              // 1/max(||w_row||, eps)
__device__ float g_cos[(size_t)NCLS * BATCH];  // [class][n] max-over-subcenter cosine
__device__ float g_pm[NCHUNK * BATCH];
__device__ float g_ps[NCHUNK * BATCH];
__device__ float g_lab_logit[BATCH];
__device__ int   g_labels[BATCH];

// ---------------- label decode (int32 vs int64 robust) ---------------------
__global__ void k_decode_labels(const int* __restrict__ p) {
    __shared__ int any_nonzero;
    int t = threadIdx.x;
    if (t == 0) any_nonzero = 0;
    __syncthreads();
    // First 256 int32 words are in-bounds for both layouts (>=1KB buffer).
    // int64 layout: odd words are high halves == 0 (labels < 100000).
    if (t < 128) {
        if (p[2 * t + 1] != 0) any_nonzero = 1;
    }
    __syncthreads();
    if (any_nonzero) g_labels[t] = p[t];        // int32 labels
    else             g_labels[t] = p[2 * t];    // int64 labels (low word)
}

// ---------------- embedding normalize (transposed output) ------------------
__global__ void k_norm_emb(const float* __restrict__ emb) {
    int n = blockIdx.x, tid = threadIdx.x;     // 128 threads
    float v[4];
    float ss = 0.f;
#pragma unroll
    for (int i = 0; i < 4; i++) {
        v[i] = emb[n * DIM + tid + i * 128];
        ss += v[i] * v[i];
    }
#pragma unroll
    for (int o = 16; o; o >>= 1) ss += __shfl_xor_sync(0xffffffffu, ss, o);
    __shared__ float swarp[4];
    __shared__ float sinv;
    if ((tid & 31) == 0) swarp[tid >> 5] = ss;
    __syncthreads();
    if (tid == 0)
        sinv = 1.f / fmaxf(sqrtf(swarp[0] + swarp[1] + swarp[2] + swarp[3]), 1e-12f);
    __syncthreads();
    float inv = sinv;
#pragma unroll
    for (int i = 0; i < 4; i++)
        g_eT[(tid + i * 128) * BATCH + n] = v[i] * inv;
}

// ---------------- weight row inverse norms (warp per row) ------------------
__global__ void k_wnorm(const float* __restrict__ W) {
    int warp = threadIdx.x >> 5, lane = threadIdx.x & 31;
    int row = blockIdx.x * 8 + warp;
    const float4* p = (const float4*)(W + (size_t)row * DIM);
    float ss = 0.f;
#pragma unroll
    for (int i = 0; i < 4; i++) {
        float4 q = p[lane + i * 32];
        ss += q.x * q.x + q.y * q.y + q.z * q.z + q.w * q.w;
    }
#pragma unroll
    for (int o = 16; o; o >>= 1) ss += __shfl_xor_sync(0xffffffffu, ss, o);
    if (lane == 0) g_inv_wn[row] = 1.f / fmaxf(sqrtf(ss), 1e-12f);
}

// ---------------- fused cosine GEMM + subcenter max ------------------------
// Block: 48 weight rows (16 classes) x all 256 batch cols, K = 512.
// 256 threads: tm = tid/32 (8 row-groups of 6 rows), tn = tid%32 (8 cols each).
__global__ void __launch_bounds__(256, 2) k_gemm(const float* __restrict__ W) {
    __shared__ float As[BK][BM + 1];   // [k][m], padded: conflict-free
    __shared__ float Bs[BK][BATCH];    // [k][n]
    int tid = threadIdx.x;
    int m0 = blockIdx.x * BM;
    int tm = tid >> 5, tn = tid & 31;
    const float* Wb = W + (size_t)m0 * DIM;

    float acc[6][8];
#pragma unroll
    for (int i = 0; i < 6; i++)
#pragma unroll
        for (int j = 0; j < 8; j++) acc[i][j] = 0.f;

    for (int k0 = 0; k0 < DIM; k0 += BK) {
        // A tile: 48x32, coalesced global reads, transposed store
#pragma unroll
        for (int i = 0; i < 6; i++) {
            int e = tid + i * 256;
            int r = e >> 5, c = e & 31;
            As[c][r] = Wb[(size_t)r * DIM + k0 + c];
        }
        // B tile: 32x256, fully coalesced (eT is [k][n])
#pragma unroll
        for (int i = 0; i < BK; i++)
            Bs[i][tid] = g_eT[(k0 + i) * BATCH + tid];
        __syncthreads();

#pragma unroll
        for (int kk = 0; kk < BK; kk++) {
            float a[6], b[8];
#pragma unroll
            for (int i = 0; i < 6; i++) a[i] = As[kk][tm * 6 + i];  // broadcast
            float4 b0 = *(const float4*)&Bs[kk][tn * 8];
            float4 b1 = *(const float4*)&Bs[kk][tn * 8 + 4];
            b[0] = b0.x; b[1] = b0.y; b[2] = b0.z; b[3] = b0.w;
            b[4] = b1.x; b[5] = b1.y; b[6] = b1.z; b[7] = b1.w;
#pragma unroll
            for (int i = 0; i < 6; i++)
#pragma unroll
                for (int j = 0; j < 8; j++)
                    acc[i][j] = fmaf(a[i], b[j], acc[i][j]);
        }
        __syncthreads();
    }

    // Epilogue: apply weight inv-norm, max over 3 subcenters, coalesced store
    float inv[6];
#pragma unroll
    for (int i = 0; i < 6; i++) inv[i] = g_inv_wn[m0 + tm * 6 + i];
    int cls0 = (m0 + tm * 6) / 3;   // tm*6 divisible by 3: 2 whole classes
#pragma unroll
    for (int cl = 0; cl < 2; cl++) {
        int b = cl * 3;
        float out[8];
#pragma unroll
        for (int j = 0; j < 8; j++) {
            float c0 = acc[b][j] * inv[b];
            float c1 = acc[b + 1][j] * inv[b + 1];
            float c2 = acc[b + 2][j] * inv[b + 2];
            out[j] = fmaxf(c0, fmaxf(c1, c2));
        }
        float* dst = &g_cos[(size_t)(cls0 + cl) * BATCH + tn * 8];
        *(float4*)dst       = make_float4(out[0], out[1], out[2], out[3]);
        *(float4*)(dst + 4) = make_float4(out[4], out[5], out[6], out[7]);
    }
}

// ---------------- chunked online logsumexp with ArcFace margin -------------
__global__ void k_lse(void) {
    int t = threadIdx.x;               // batch index
    int c0 = blockIdx.x * CPC;
    int c1 = c0 + CPC;
    int lab = g_labels[t];
    float m = -1e30f, s = 0.f;
    for (int c = c0; c < c1; c++) {
        float cs = g_cos[(size_t)c * BATCH + t];   // coalesced across t
        float x;
        if (c == lab) {
            float sine = sqrtf(fminf(fmaxf(1.f - cs * cs, 0.f), 1.f));
            float phi = cs * COS_M - sine * SIN_M;
            if (!(cs > TH_C)) phi = cs - MM_C;
            x = SCALE_C * phi;
            g_lab_logit[t] = x;
        } else {
            x = SCALE_C * cs;
        }
        if (x > m) { s *= __expf(m - x); m = x; }
        s += __expf(x - m);
    }
    g_pm[blockIdx.x * BATCH + t] = m;
    g_ps[blockIdx.x * BATCH + t] = s;
}

// ---------------- combine partials, mean loss ------------------------------
__global__ void k_final(float* __restrict__ out) {
    int t = threadIdx.x;               // 256 threads
    float m = -1e30f, s = 0.f;
    for (int k = 0; k < NCHUNK; k++) {
        float pm = g_pm[k * BATCH + t];
        float ps = g_ps[k * BATCH + t];
        if (pm > m) { s = s * __expf(m - pm) + ps; m = pm; }
        else        { s += ps * __expf(pm - m); }
    }
    float loss = m + logf(s) - g_lab_logit[t];
#pragma unroll
    for (int o = 16; o; o >>= 1) loss += __shfl_xor_sync(0xffffffffu, loss, o);
    __shared__ float swarp[8];
    if ((t & 31) == 0) swarp[t >> 5] = loss;
    __syncthreads();
    if (t == 0) {
        float tot = 0.f;
#pragma unroll
        for (int i = 0; i < 8; i++) tot += swarp[i];
        out[0] = tot / (float)BATCH;
    }
}

// ---------------------------------------------------------------------------
extern "C" void kernel_launch(void* const* d_in, const int* in_sizes, int n_in,
                              void* d_out, int out_size) {
    const float* emb    = (const float*)d_in[0];   // [256,512] f32
    const int*   labels = (const int*)d_in[1];     // int32 or int64, decoded
    const float* W      = (const float*)d_in[2];   // [300000,512] f32

    k_decode_labels<<<1, BATCH>>>(labels);
    k_norm_emb<<<BATCH, 128>>>(emb);
    k_wnorm<<<MROWS / 8, 256>>>(W);
    k_gemm<<<MROWS / BM, 256>>>(W);
    k_lse<<<NCHUNK, BATCH>>>();
    k_final<<<1, BATCH>>>((float*)d_out);
}